// round 4
// baseline (speedup 1.0000x reference)
#include <cuda_runtime.h>

#define BATCH 2
#define SEQ   2048
#define EMB   128
#define NH    8
#define HD    16
#define NROWS (BATCH*SEQ)
#define KT    128        // keys per smem tile
#define KROW  20         // padded floats per K/V smem row (80B, conflict-free 8-way split)

// Scratch for head-split Q/K/V in [b][h][s][d] layout (d contiguous, 64B rows).
__device__ float g_Q[BATCH*NH*SEQ*HD];
__device__ float g_K[BATCH*NH*SEQ*HD];
__device__ float g_V[BATCH*NH*SEQ*HD];

typedef unsigned long long u64;

__device__ __forceinline__ u64 pack2(float lo, float hi){
    u64 r; asm("mov.b64 %0, {%1, %2};" : "=l"(r) : "f"(lo), "f"(hi)); return r;
}
__device__ __forceinline__ void unpack2(u64 v, float& a, float& b){
    asm("mov.b64 {%0, %1}, %2;" : "=f"(a), "=f"(b) : "l"(v));
}
__device__ __forceinline__ u64 fma2(u64 a, u64 b, u64 c){
    u64 d; asm("fma.rn.f32x2 %0, %1, %2, %3;" : "=l"(d) : "l"(a), "l"(b), "l"(c)); return d;
}
__device__ __forceinline__ u64 mul2(u64 a, u64 b){
    u64 d; asm("mul.rn.f32x2 %0, %1, %2;" : "=l"(d) : "l"(a), "l"(b)); return d;
}
__device__ __forceinline__ float ex2f(float x){
    float y; asm("ex2.approx.ftz.f32 %0, %1;" : "=f"(y) : "f"(x)); return y;
}

// ---------------------------------------------------------------------------
// Kernel 1: fused QKV projection + head split (unchanged).
// ---------------------------------------------------------------------------
__global__ __launch_bounds__(256) void qkv_kernel(
    const float* __restrict__ X,
    const float* __restrict__ Wq, const float* __restrict__ Wk,
    const float* __restrict__ Wv)
{
    __shared__ __align__(16) float Xs[32][EMB];
    const int r0 = blockIdx.x * 32;
    {
        const float4* xg = (const float4*)(X + (size_t)r0 * EMB);
        float4* xs = (float4*)&Xs[0][0];
        #pragma unroll
        for (int i = 0; i < 4; i++)
            xs[threadIdx.x + 256 * i] = xg[threadIdx.x + 256 * i];
    }
    __syncthreads();

    const int oc = threadIdx.x & 31;
    const int c4 = oc * 4;
    const int rg = threadIdx.x >> 5;

    float aq[4][4], ak[4][4], av[4][4];
    #pragma unroll
    for (int i = 0; i < 4; i++)
        #pragma unroll
        for (int j = 0; j < 4; j++) { aq[i][j] = 0.f; ak[i][j] = 0.f; av[i][j] = 0.f; }

    for (int e0 = 0; e0 < EMB; e0 += 4) {
        float4 xr[4];
        #pragma unroll
        for (int i = 0; i < 4; i++)
            xr[i] = *(const float4*)&Xs[rg * 4 + i][e0];
        #pragma unroll
        for (int ee = 0; ee < 4; ee++) {
            const int e = e0 + ee;
            float4 wq = *(const float4*)(Wq + e * EMB + c4);
            float4 wk = *(const float4*)(Wk + e * EMB + c4);
            float4 wv = *(const float4*)(Wv + e * EMB + c4);
            #pragma unroll
            for (int i = 0; i < 4; i++) {
                float x = (ee == 0) ? xr[i].x : (ee == 1) ? xr[i].y
                        : (ee == 2) ? xr[i].z : xr[i].w;
                aq[i][0] += x * wq.x; aq[i][1] += x * wq.y;
                aq[i][2] += x * wq.z; aq[i][3] += x * wq.w;
                ak[i][0] += x * wk.x; ak[i][1] += x * wk.y;
                ak[i][2] += x * wk.z; ak[i][3] += x * wk.w;
                av[i][0] += x * wv.x; av[i][1] += x * wv.y;
                av[i][2] += x * wv.z; av[i][3] += x * wv.w;
            }
        }
    }

    #pragma unroll
    for (int i = 0; i < 4; i++) {
        const int r = r0 + rg * 4 + i;
        const int b = r >> 11;
        const int s = r & (SEQ - 1);
        #pragma unroll
        for (int j = 0; j < 4; j++) {
            const int c = c4 + j;
            const int h = c & 7;
            const int d = c >> 3;
            const int idx = (((b * NH + h) * SEQ + s) * HD) + d;
            g_Q[idx] = aq[i][j];
            g_K[idx] = ak[i][j];
            g_V[idx] = av[i][j];
        }
    }
}

// ---------------------------------------------------------------------------
// Kernel 2: flash attention, 2 queries per thread, 8-way KV split.
// Grid (SEQ/32, BATCH*NH) = (64,16) -> 1024 CTAs, 128 threads (4 warps).
// Lane l: query-pair id = l&3, split = l>>2 processes keys (8*j + spl).
// KROW=20 padding -> the 8 splits' simultaneous 16B reads hit disjoint banks.
// Partials merged via 3 butterfly shfl rounds (offsets 4, 8, 16).
// ---------------------------------------------------------------------------
__global__ __launch_bounds__(128, 6) void attn_kernel(
    const int* __restrict__ mask_src, float* __restrict__ out)
{
    __shared__ __align__(16) float Ks[KT * KROW];
    __shared__ __align__(16) float Vs[KT * KROW];
    __shared__ float addm[KT];

    const int tid  = threadIdx.x;
    const int w    = tid >> 5;
    const int lane = tid & 31;
    const int spl  = lane >> 2;          // 0..7
    const int bh = blockIdx.y;
    const int b  = bh >> 3;
    const int h  = bh & 7;
    const int qA = blockIdx.x * 32 + w * 8 + (lane & 3) * 2;
    const int qB = qA + 1;

    const float* Qb = g_Q + (size_t)bh * SEQ * HD;
    const float* Kb = g_K + (size_t)bh * SEQ * HD;
    const float* Vb = g_V + (size_t)bh * SEQ * HD;

    // q scaled by log2(e)/sqrt(HD)
    u64 qa2[8], qb2[8];
    {
        const float SC = 0.3606737602222409f;  // 1.4426950408889634 / 4
        const float4* pa = (const float4*)(Qb + qA * HD);
        const float4* pb = (const float4*)(Qb + qB * HD);
        #pragma unroll
        for (int i = 0; i < 4; i++) {
            float4 va = pa[i], vb = pb[i];
            qa2[2*i]   = pack2(va.x * SC, va.y * SC);
            qa2[2*i+1] = pack2(va.z * SC, va.w * SC);
            qb2[2*i]   = pack2(vb.x * SC, vb.y * SC);
            qb2[2*i+1] = pack2(vb.z * SC, vb.w * SC);
        }
    }

    float mA = -1e30f, lA = 0.f, mB = -1e30f, lB = 0.f;
    u64 accA[8], accB[8];
    #pragma unroll
    for (int i = 0; i < 8; i++) { accA[i] = pack2(0.f, 0.f); accB[i] = pack2(0.f, 0.f); }

    const float NEGM = -1442.6950408889634f;  // -1000 * log2(e)

    for (int kb = 0; kb < SEQ; kb += KT) {
        __syncthreads();
        {
            const float4* kg = (const float4*)(Kb + kb * HD);
            const float4* vg = (const float4*)(Vb + kb * HD);
            #pragma unroll
            for (int i = 0; i < 4; i++) {
                const int idx = tid + 128 * i;      // float4 index, 512 total
                const int row = idx >> 2;
                const int c4  = (idx & 3) * 4;
                *(float4*)&Ks[row * KROW + c4] = kg[idx];
                *(float4*)&Vs[row * KROW + c4] = vg[idx];
            }
            addm[tid] = mask_src[b * SEQ + kb + tid] ? 0.f : NEGM;
        }
        __syncthreads();

        // This split's keys: local index 8*j + spl, j in [0,16), chunks of 8.
        #pragma unroll
        for (int c = 0; c < 16; c += 8) {
            float sA[8], sB[8];
            float cmA = -1e30f, cmB = -1e30f;
            #pragma unroll
            for (int kk = 0; kk < 8; kk++) {
                const int krow = ((c + kk) << 3) + spl;
                const double2* kr = (const double2*)(Ks + krow * KROW);
                double2 p0 = kr[0], p1 = kr[1];
                u64 tA = mul2(qa2[0], __double_as_longlong(p0.x));
                u64 tB = mul2(qb2[0], __double_as_longlong(p0.x));
                tA = fma2(qa2[1], __double_as_longlong(p0.y), tA);
                tB = fma2(qb2[1], __double_as_longlong(p0.y), tB);
                tA = fma2(qa2[2], __double_as_longlong(p1.x), tA);
                tB = fma2(qb2[2], __double_as_longlong(p1.x), tB);
                tA = fma2(qa2[3], __double_as_longlong(p1.y), tA);
                tB = fma2(qb2[3], __double_as_longlong(p1.y), tB);
                double2 p2 = kr[2], p3 = kr[3];
                tA = fma2(qa2[4], __double_as_longlong(p2.x), tA);
                tB = fma2(qb2[4], __double_as_longlong(p2.x), tB);
                tA = fma2(qa2[5], __double_as_longlong(p2.y), tA);
                tB = fma2(qb2[5], __double_as_longlong(p2.y), tB);
                tA = fma2(qa2[6], __double_as_longlong(p3.x), tA);
                tB = fma2(qb2[6], __double_as_longlong(p3.x), tB);
                tA = fma2(qa2[7], __double_as_longlong(p3.y), tA);
                tB = fma2(qb2[7], __double_as_longlong(p3.y), tB);
                const float am = addm[krow];
                float ta0, ta1, tb0, tb1;
                unpack2(tA, ta0, ta1);
                unpack2(tB, tb0, tb1);
                const float svA = ta0 + ta1 + am;
                const float svB = tb0 + tb1 + am;
                sA[kk] = svA;  cmA = fmaxf(cmA, svA);
                sB[kk] = svB;  cmB = fmaxf(cmB, svB);
            }
            // Only rescale when some lane's running max changed (rare after warmup).
            const bool upd = (cmA > mA) || (cmB > mB);
            if (__any_sync(0xFFFFFFFFu, upd)) {
                const float nmA = fmaxf(mA, cmA);
                const float coA = ex2f(mA - nmA);
                lA *= coA;  mA = nmA;
                const u64 cA2 = pack2(coA, coA);
                const float nmB = fmaxf(mB, cmB);
                const float coB = ex2f(mB - nmB);
                lB *= coB;  mB = nmB;
                const u64 cB2 = pack2(coB, coB);
                #pragma unroll
                for (int i = 0; i < 8; i++) {
                    accA[i] = mul2(accA[i], cA2);
                    accB[i] = mul2(accB[i], cB2);
                }
            }
            #pragma unroll
            for (int kk = 0; kk < 8; kk++) {
                const float pA = ex2f(sA[kk] - mA);
                const float pB = ex2f(sB[kk] - mB);
                lA += pA;  lB += pB;
                const u64 ppA = pack2(pA, pA);
                const u64 ppB = pack2(pB, pB);
                const int krow = ((c + kk) << 3) + spl;
                const double2* vr = (const double2*)(Vs + krow * KROW);
                double2 v0 = vr[0], v1 = vr[1];
                accA[0] = fma2(ppA, __double_as_longlong(v0.x), accA[0]);
                accB[0] = fma2(ppB, __double_as_longlong(v0.x), accB[0]);
                accA[1] = fma2(ppA, __double_as_longlong(v0.y), accA[1]);
                accB[1] = fma2(ppB, __double_as_longlong(v0.y), accB[1]);
                accA[2] = fma2(ppA, __double_as_longlong(v1.x), accA[2]);
                accB[2] = fma2(ppB, __double_as_longlong(v1.x), accB[2]);
                accA[3] = fma2(ppA, __double_as_longlong(v1.y), accA[3]);
                accB[3] = fma2(ppB, __double_as_longlong(v1.y), accB[3]);
                double2 v2 = vr[2], v3 = vr[3];
                accA[4] = fma2(ppA, __double_as_longlong(v2.x), accA[4]);
                accB[4] = fma2(ppB, __double_as_longlong(v2.x), accB[4]);
                accA[5] = fma2(ppA, __double_as_longlong(v2.y), accA[5]);
                accB[5] = fma2(ppB, __double_as_longlong(v2.y), accB[5]);
                accA[6] = fma2(ppA, __double_as_longlong(v3.x), accA[6]);
                accB[6] = fma2(ppB, __double_as_longlong(v3.x), accB[6]);
                accA[7] = fma2(ppA, __double_as_longlong(v3.y), accA[7]);
                accB[7] = fma2(ppB, __double_as_longlong(v3.y), accB[7]);
            }
        }
    }

    // Combine the 8 split partials (lanes l ^ {4,8,16} hold same query pair).
    float fA[16], fB[16];
    #pragma unroll
    for (int i = 0; i < 8; i++) {
        unpack2(accA[i], fA[2*i], fA[2*i+1]);
        unpack2(accB[i], fB[2*i], fB[2*i+1]);
    }

    #pragma unroll
    for (int off = 4; off <= 16; off <<= 1) {
        {
            const float mo = __shfl_xor_sync(0xFFFFFFFFu, mA, off);
            const float M  = fmaxf(mA, mo);
            const float c  = ex2f(mA - M);
            mA = M;  lA *= c;
            lA += __shfl_xor_sync(0xFFFFFFFFu, lA, off);
            #pragma unroll
            for (int i = 0; i < 16; i++) {
                fA[i] *= c;
                fA[i] += __shfl_xor_sync(0xFFFFFFFFu, fA[i], off);
            }
        }
        {
            const float mo = __shfl_xor_sync(0xFFFFFFFFu, mB, off);
            const float M  = fmaxf(mB, mo);
            const float c  = ex2f(mB - M);
            mB = M;  lB *= c;
            lB += __shfl_xor_sync(0xFFFFFFFFu, lB, off);
            #pragma unroll
            for (int i = 0; i < 16; i++) {
                fB[i] *= c;
                fB[i] += __shfl_xor_sync(0xFFFFFFFFu, fB[i], off);
            }
        }
    }

    if (spl == 0) {
        // out[b][s][d*NH + h] = f[d] / l   (inverse head split)
        const float iA = 1.f / lA;
        const float iB = 1.f / lB;
        float* opA = out + ((size_t)(b * SEQ + qA)) * EMB + h;
        float* opB = out + ((size_t)(b * SEQ + qB)) * EMB + h;
        #pragma unroll
        for (int j = 0; j < 16; j++) {
            opA[j * NH] = fA[j] * iA;
            opB[j * NH] = fB[j] * iB;
        }
    }
}

extern "C" void kernel_launch(void* const* d_in, const int* in_sizes, int n_in,
                              void* d_out, int out_size)
{
    const float* X    = (const float*)d_in[0];
    const int*   msk  = (const int*)d_in[1];
    // d_in[2] = target mask (unused, encoder path), d_in[3] = masked flag (0)
    const float* Wq   = (const float*)d_in[4];
    const float* Wk   = (const float*)d_in[5];
    const float* Wv   = (const float*)d_in[6];
    float* out        = (float*)d_out;

    qkv_kernel<<<NROWS / 32, 256>>>(X, Wq, Wk, Wv);

    dim3 grid(SEQ / 32, BATCH * NH);
    attn_kernel<<<grid, 128>>>(msk, out);
}

// round 5
// speedup vs baseline: 1.4999x; 1.4999x over previous
#include <cuda_runtime.h>

#define BATCH 2
#define SEQ   2048
#define EMB   128
#define NH    8
#define HD    16
#define NROWS (BATCH*SEQ)
#define KT    128        // keys per smem tile
#define KROW  20         // padded floats per K/V smem row (80B, conflict-free 4-way split)
#define NKV   4          // KV splits across CTAs
#define KEYS_PER_CTA (SEQ/NKV)   // 512
#define PREC  20         // floats per partial record (16 acc, m, l, pad)

// Scratch for head-split Q/K/V in [b][h][s][d] layout (d contiguous, 64B rows).
__device__ float g_Q[BATCH*NH*SEQ*HD];
__device__ float g_K[BATCH*NH*SEQ*HD];
__device__ float g_V[BATCH*NH*SEQ*HD];
// Partials: [query_row(32768)][kv_split(4)][PREC]
__device__ float g_part[BATCH*NH*SEQ*NKV*PREC];

typedef unsigned long long u64;

__device__ __forceinline__ u64 pack2(float lo, float hi){
    u64 r; asm("mov.b64 %0, {%1, %2};" : "=l"(r) : "f"(lo), "f"(hi)); return r;
}
__device__ __forceinline__ void unpack2(u64 v, float& a, float& b){
    asm("mov.b64 {%0, %1}, %2;" : "=f"(a), "=f"(b) : "l"(v));
}
__device__ __forceinline__ u64 fma2(u64 a, u64 b, u64 c){
    u64 d; asm("fma.rn.f32x2 %0, %1, %2, %3;" : "=l"(d) : "l"(a), "l"(b), "l"(c)); return d;
}
__device__ __forceinline__ u64 mul2(u64 a, u64 b){
    u64 d; asm("mul.rn.f32x2 %0, %1, %2;" : "=l"(d) : "l"(a), "l"(b)); return d;
}
__device__ __forceinline__ float ex2f(float x){
    float y; asm("ex2.approx.ftz.f32 %0, %1;" : "=f"(y) : "f"(x)); return y;
}

// ---------------------------------------------------------------------------
// Kernel 1: fused QKV projection + head split (unchanged).
// ---------------------------------------------------------------------------
__global__ __launch_bounds__(256) void qkv_kernel(
    const float* __restrict__ X,
    const float* __restrict__ Wq, const float* __restrict__ Wk,
    const float* __restrict__ Wv)
{
    __shared__ __align__(16) float Xs[32][EMB];
    const int r0 = blockIdx.x * 32;
    {
        const float4* xg = (const float4*)(X + (size_t)r0 * EMB);
        float4* xs = (float4*)&Xs[0][0];
        #pragma unroll
        for (int i = 0; i < 4; i++)
            xs[threadIdx.x + 256 * i] = xg[threadIdx.x + 256 * i];
    }
    __syncthreads();

    const int oc = threadIdx.x & 31;
    const int c4 = oc * 4;
    const int rg = threadIdx.x >> 5;

    float aq[4][4], ak[4][4], av[4][4];
    #pragma unroll
    for (int i = 0; i < 4; i++)
        #pragma unroll
        for (int j = 0; j < 4; j++) { aq[i][j] = 0.f; ak[i][j] = 0.f; av[i][j] = 0.f; }

    for (int e0 = 0; e0 < EMB; e0 += 4) {
        float4 xr[4];
        #pragma unroll
        for (int i = 0; i < 4; i++)
            xr[i] = *(const float4*)&Xs[rg * 4 + i][e0];
        #pragma unroll
        for (int ee = 0; ee < 4; ee++) {
            const int e = e0 + ee;
            float4 wq = *(const float4*)(Wq + e * EMB + c4);
            float4 wk = *(const float4*)(Wk + e * EMB + c4);
            float4 wv = *(const float4*)(Wv + e * EMB + c4);
            #pragma unroll
            for (int i = 0; i < 4; i++) {
                float x = (ee == 0) ? xr[i].x : (ee == 1) ? xr[i].y
                        : (ee == 2) ? xr[i].z : xr[i].w;
                aq[i][0] += x * wq.x; aq[i][1] += x * wq.y;
                aq[i][2] += x * wq.z; aq[i][3] += x * wq.w;
                ak[i][0] += x * wk.x; ak[i][1] += x * wk.y;
                ak[i][2] += x * wk.z; ak[i][3] += x * wk.w;
                av[i][0] += x * wv.x; av[i][1] += x * wv.y;
                av[i][2] += x * wv.z; av[i][3] += x * wv.w;
            }
        }
    }

    #pragma unroll
    for (int i = 0; i < 4; i++) {
        const int r = r0 + rg * 4 + i;
        const int b = r >> 11;
        const int s = r & (SEQ - 1);
        #pragma unroll
        for (int j = 0; j < 4; j++) {
            const int c = c4 + j;
            const int h = c & 7;
            const int d = c >> 3;
            const int idx = (((b * NH + h) * SEQ + s) * HD) + d;
            g_Q[idx] = aq[i][j];
            g_K[idx] = ak[i][j];
            g_V[idx] = av[i][j];
        }
    }
}

// ---------------------------------------------------------------------------
// Kernel 2: flash attention partial. 2 queries/thread, 4-way lane KV split,
// 4-way CTA KV split. Grid (32, 16, 4), 128 threads (4 warps).
// Warp w, lane l: queries qA=blk*64+w*16+(l&7)*2, qB=qA+1; split=l>>3 handles
// keys (4*j + spl) of each tile; CTA z handles keys [z*512, z*512+512).
// Each lane writes its (m, l, acc) partial; combine_kernel merges the 4 lane
// splits x ... no: lane splits merged by shfl? NO — all 4 lane-splits AND the
// CTA split write partials? Lane splits are merged via shfl (cheap, in-warp);
// only the 4 CTA splits go through g_part.
// ---------------------------------------------------------------------------
__global__ __launch_bounds__(128, 5) void attn_kernel(
    const int* __restrict__ mask_src)
{
    __shared__ __align__(16) float Ks[KT * KROW];
    __shared__ __align__(16) float Vs[KT * KROW];
    __shared__ float addm[KT];

    const int tid  = threadIdx.x;
    const int w    = tid >> 5;
    const int lane = tid & 31;
    const int spl  = lane >> 3;          // 0..3 (in-warp key split)
    const int bh   = blockIdx.y;
    const int b    = bh >> 3;
    const int z    = blockIdx.z;         // CTA KV split 0..3
    const int qA = blockIdx.x * 64 + w * 16 + (lane & 7) * 2;
    const int qB = qA + 1;

    const float* Qb = g_Q + (size_t)bh * SEQ * HD;
    const float* Kb = g_K + (size_t)bh * SEQ * HD;
    const float* Vb = g_V + (size_t)bh * SEQ * HD;

    // q scaled by log2(e)/sqrt(HD)
    u64 qa2[8], qb2[8];
    {
        const float SC = 0.3606737602222409f;  // 1.4426950408889634 / 4
        const float4* pa = (const float4*)(Qb + qA * HD);
        const float4* pb = (const float4*)(Qb + qB * HD);
        #pragma unroll
        for (int i = 0; i < 4; i++) {
            float4 va = pa[i], vb = pb[i];
            qa2[2*i]   = pack2(va.x * SC, va.y * SC);
            qa2[2*i+1] = pack2(va.z * SC, va.w * SC);
            qb2[2*i]   = pack2(vb.x * SC, vb.y * SC);
            qb2[2*i+1] = pack2(vb.z * SC, vb.w * SC);
        }
    }

    float mA = -1e30f, lA = 0.f, mB = -1e30f, lB = 0.f;
    u64 accA[8], accB[8];
    #pragma unroll
    for (int i = 0; i < 8; i++) { accA[i] = pack2(0.f, 0.f); accB[i] = pack2(0.f, 0.f); }

    const float NEGM = -1442.6950408889634f;  // -1000 * log2(e)

    const int kb0 = z * KEYS_PER_CTA;
    for (int kb = kb0; kb < kb0 + KEYS_PER_CTA; kb += KT) {
        __syncthreads();
        {
            const float4* kg = (const float4*)(Kb + kb * HD);
            const float4* vg = (const float4*)(Vb + kb * HD);
            #pragma unroll
            for (int i = 0; i < 4; i++) {
                const int idx = tid + 128 * i;      // float4 index, 512 total
                const int row = idx >> 2;
                const int c4  = (idx & 3) * 4;
                *(float4*)&Ks[row * KROW + c4] = kg[idx];
                *(float4*)&Vs[row * KROW + c4] = vg[idx];
            }
            addm[tid] = mask_src[b * SEQ + kb + tid] ? 0.f : NEGM;
        }
        __syncthreads();

        // This split's keys: local index 4*j + spl, j in [0,32), chunks of 8.
        #pragma unroll
        for (int c = 0; c < 32; c += 8) {
            float sA[8], sB[8];
            float cmA = -1e30f, cmB = -1e30f;
            #pragma unroll
            for (int kk = 0; kk < 8; kk++) {
                const int krow = ((c + kk) << 2) + spl;
                const double2* kr = (const double2*)(Ks + krow * KROW);
                double2 p0 = kr[0], p1 = kr[1], p2 = kr[2], p3 = kr[3];
                const u64 k0 = __double_as_longlong(p0.x), k1 = __double_as_longlong(p0.y);
                const u64 k2 = __double_as_longlong(p1.x), k3 = __double_as_longlong(p1.y);
                const u64 k4 = __double_as_longlong(p2.x), k5 = __double_as_longlong(p2.y);
                const u64 k6 = __double_as_longlong(p3.x), k7 = __double_as_longlong(p3.y);
                u64 tA = mul2(qa2[0], k0);
                u64 tB = mul2(qb2[0], k0);
                tA = fma2(qa2[1], k1, tA);  tB = fma2(qb2[1], k1, tB);
                tA = fma2(qa2[2], k2, tA);  tB = fma2(qb2[2], k2, tB);
                tA = fma2(qa2[3], k3, tA);  tB = fma2(qb2[3], k3, tB);
                tA = fma2(qa2[4], k4, tA);  tB = fma2(qb2[4], k4, tB);
                tA = fma2(qa2[5], k5, tA);  tB = fma2(qb2[5], k5, tB);
                tA = fma2(qa2[6], k6, tA);  tB = fma2(qb2[6], k6, tB);
                tA = fma2(qa2[7], k7, tA);  tB = fma2(qb2[7], k7, tB);
                const float am = addm[krow];
                float ta0, ta1, tb0, tb1;
                unpack2(tA, ta0, ta1);
                unpack2(tB, tb0, tb1);
                const float svA = ta0 + ta1 + am;
                const float svB = tb0 + tb1 + am;
                sA[kk] = svA;  cmA = fmaxf(cmA, svA);
                sB[kk] = svB;  cmB = fmaxf(cmB, svB);
            }
            // Only rescale when some lane's running max changed.
            const bool upd = (cmA > mA) || (cmB > mB);
            if (__any_sync(0xFFFFFFFFu, upd)) {
                const float nmA = fmaxf(mA, cmA);
                const float coA = ex2f(mA - nmA);
                lA *= coA;  mA = nmA;
                const u64 cA2 = pack2(coA, coA);
                const float nmB = fmaxf(mB, cmB);
                const float coB = ex2f(mB - nmB);
                lB *= coB;  mB = nmB;
                const u64 cB2 = pack2(coB, coB);
                #pragma unroll
                for (int i = 0; i < 8; i++) {
                    accA[i] = mul2(accA[i], cA2);
                    accB[i] = mul2(accB[i], cB2);
                }
            }
            #pragma unroll
            for (int kk = 0; kk < 8; kk++) {
                const float pA = ex2f(sA[kk] - mA);
                const float pB = ex2f(sB[kk] - mB);
                lA += pA;  lB += pB;
                const u64 ppA = pack2(pA, pA);
                const u64 ppB = pack2(pB, pB);
                const int krow = ((c + kk) << 2) + spl;
                const double2* vr = (const double2*)(Vs + krow * KROW);
                double2 v0 = vr[0], v1 = vr[1], v2 = vr[2], v3 = vr[3];
                const u64 w0 = __double_as_longlong(v0.x), w1 = __double_as_longlong(v0.y);
                const u64 w2 = __double_as_longlong(v1.x), w3 = __double_as_longlong(v1.y);
                const u64 w4 = __double_as_longlong(v2.x), w5 = __double_as_longlong(v2.y);
                const u64 w6 = __double_as_longlong(v3.x), w7 = __double_as_longlong(v3.y);
                accA[0] = fma2(ppA, w0, accA[0]);  accB[0] = fma2(ppB, w0, accB[0]);
                accA[1] = fma2(ppA, w1, accA[1]);  accB[1] = fma2(ppB, w1, accB[1]);
                accA[2] = fma2(ppA, w2, accA[2]);  accB[2] = fma2(ppB, w2, accB[2]);
                accA[3] = fma2(ppA, w3, accA[3]);  accB[3] = fma2(ppB, w3, accB[3]);
                accA[4] = fma2(ppA, w4, accA[4]);  accB[4] = fma2(ppB, w4, accB[4]);
                accA[5] = fma2(ppA, w5, accA[5]);  accB[5] = fma2(ppB, w5, accB[5]);
                accA[6] = fma2(ppA, w6, accA[6]);  accB[6] = fma2(ppB, w6, accB[6]);
                accA[7] = fma2(ppA, w7, accA[7]);  accB[7] = fma2(ppB, w7, accB[7]);
            }
        }
    }

    // Merge the 4 in-warp lane splits via 2 butterfly shfl rounds.
    float fA[16], fB[16];
    #pragma unroll
    for (int i = 0; i < 8; i++) {
        unpack2(accA[i], fA[2*i], fA[2*i+1]);
        unpack2(accB[i], fB[2*i], fB[2*i+1]);
    }

    #pragma unroll
    for (int off = 8; off <= 16; off <<= 1) {
        {
            const float mo = __shfl_xor_sync(0xFFFFFFFFu, mA, off);
            const float M  = fmaxf(mA, mo);
            const float c  = ex2f(mA - M);
            mA = M;  lA *= c;
            lA += __shfl_xor_sync(0xFFFFFFFFu, lA, off);
            #pragma unroll
            for (int i = 0; i < 16; i++) {
                fA[i] *= c;
                fA[i] += __shfl_xor_sync(0xFFFFFFFFu, fA[i], off);
            }
        }
        {
            const float mo = __shfl_xor_sync(0xFFFFFFFFu, mB, off);
            const float M  = fmaxf(mB, mo);
            const float c  = ex2f(mB - M);
            mB = M;  lB *= c;
            lB += __shfl_xor_sync(0xFFFFFFFFu, lB, off);
            #pragma unroll
            for (int i = 0; i < 16; i++) {
                fB[i] *= c;
                fB[i] += __shfl_xor_sync(0xFFFFFFFFu, fB[i], off);
            }
        }
    }

    // spl==0 lanes write the CTA-split partial records for qA and qB.
    if (spl == 0) {
        float* pa = g_part + ((size_t)(bh * SEQ + qA) * NKV + z) * PREC;
        float* pb = g_part + ((size_t)(bh * SEQ + qB) * NKV + z) * PREC;
        #pragma unroll
        for (int i = 0; i < 4; i++) {
            *(float4*)(pa + 4 * i) = make_float4(fA[4*i], fA[4*i+1], fA[4*i+2], fA[4*i+3]);
            *(float4*)(pb + 4 * i) = make_float4(fB[4*i], fB[4*i+1], fB[4*i+2], fB[4*i+3]);
        }
        *(float4*)(pa + 16) = make_float4(mA, lA, 0.f, 0.f);
        *(float4*)(pb + 16) = make_float4(mB, lB, 0.f, 0.f);
    }
}

// ---------------------------------------------------------------------------
// Kernel 3: merge NKV partials per query row, write final output.
// One thread per query row (32768 threads).
// ---------------------------------------------------------------------------
__global__ __launch_bounds__(128) void combine_kernel(float* __restrict__ out)
{
    const int idx = blockIdx.x * 128 + threadIdx.x;   // 0..32767: bh*SEQ + q
    const float* p = g_part + (size_t)idx * NKV * PREC;

    float m0, m1, m2, m3;
    {
        float4 t0 = *(const float4*)(p + 16);
        float4 t1 = *(const float4*)(p + PREC + 16);
        float4 t2 = *(const float4*)(p + 2*PREC + 16);
        float4 t3 = *(const float4*)(p + 3*PREC + 16);
        m0 = t0.x; m1 = t1.x; m2 = t2.x; m3 = t3.x;
        const float M = fmaxf(fmaxf(m0, m1), fmaxf(m2, m3));
        const float w0 = ex2f(m0 - M), w1 = ex2f(m1 - M);
        const float w2 = ex2f(m2 - M), w3 = ex2f(m3 - M);
        const float denom = t0.y * w0 + t1.y * w1 + t2.y * w2 + t3.y * w3;
        const float inv = 1.f / denom;

        const int bh = idx >> 11;            // / SEQ
        const int q  = idx & (SEQ - 1);
        const int b  = bh >> 3;
        const int h  = bh & 7;
        float* op = out + ((size_t)(b * SEQ + q)) * EMB + h;

        #pragma unroll
        for (int i = 0; i < 4; i++) {
            float4 a0 = *(const float4*)(p + 4 * i);
            float4 a1 = *(const float4*)(p + PREC + 4 * i);
            float4 a2 = *(const float4*)(p + 2*PREC + 4 * i);
            float4 a3 = *(const float4*)(p + 3*PREC + 4 * i);
            op[(4*i+0) * NH] = (a0.x*w0 + a1.x*w1 + a2.x*w2 + a3.x*w3) * inv;
            op[(4*i+1) * NH] = (a0.y*w0 + a1.y*w1 + a2.y*w2 + a3.y*w3) * inv;
            op[(4*i+2) * NH] = (a0.z*w0 + a1.z*w1 + a2.z*w2 + a3.z*w3) * inv;
            op[(4*i+3) * NH] = (a0.w*w0 + a1.w*w1 + a2.w*w2 + a3.w*w3) * inv;
        }
    }
}

extern "C" void kernel_launch(void* const* d_in, const int* in_sizes, int n_in,
                              void* d_out, int out_size)
{
    const float* X    = (const float*)d_in[0];
    const int*   msk  = (const int*)d_in[1];
    // d_in[2] = target mask (unused, encoder path), d_in[3] = masked flag (0)
    const float* Wq   = (const float*)d_in[4];
    const float* Wk   = (const float*)d_in[5];
    const float* Wv   = (const float*)d_in[6];
    float* out        = (float*)d_out;

    qkv_kernel<<<NROWS / 32, 256>>>(X, Wq, Wk, Wv);

    dim3 grid(SEQ / 64, BATCH * NH, NKV);
    attn_kernel<<<grid, 128>>>(msk);

    combine_kernel<<<BATCH * NH * SEQ / 128, 128>>>(out);
}